// round 11
// baseline (speedup 1.0000x reference)
#include <cuda_runtime.h>
#include <cuda_fp16.h>
#include <math.h>

#define B_  16
#define T_  2048
#define C_  768
#define H_  64
#define BT_ (B_*T_)

// Scratch (allocation-free rule: device globals) — all fp16-rounded
__device__ __half g_Qh[BT_*H_];
__device__ __half g_Kh[BT_*H_];
__device__ __half g_Vh[BT_*H_];
// W transposed, fp16-rounded: rows ng = m*64+n (m: 0=K,1=Q,2=V), cols k
__device__ __half g_Wt_h[192*768];

// ---------------------------------------------------------------------------
// helpers
// ---------------------------------------------------------------------------
__device__ __forceinline__ unsigned smem_u32(const void* p) {
    unsigned a;
    asm("{ .reg .u64 t; cvta.to.shared.u64 t, %1; cvt.u32.u64 %0, t; }"
        : "=r"(a) : "l"(p));
    return a;
}
__device__ __forceinline__ void ldsm4(unsigned* r, unsigned addr) {
    asm volatile("ldmatrix.sync.aligned.m8n8.x4.shared.b16 {%0,%1,%2,%3}, [%4];"
                 : "=r"(r[0]), "=r"(r[1]), "=r"(r[2]), "=r"(r[3]) : "r"(addr));
}
__device__ __forceinline__ void ldsm4_t(unsigned* r, unsigned addr) {
    asm volatile("ldmatrix.sync.aligned.m8n8.x4.trans.shared.b16 {%0,%1,%2,%3}, [%4];"
                 : "=r"(r[0]), "=r"(r[1]), "=r"(r[2]), "=r"(r[3]) : "r"(addr));
}
__device__ __forceinline__ void mma_f16(float* c, const unsigned* a, const unsigned* b) {
    asm volatile(
        "mma.sync.aligned.m16n8k16.row.col.f32.f16.f16.f32 "
        "{%0,%1,%2,%3}, {%4,%5,%6,%7}, {%8,%9}, {%0,%1,%2,%3};"
        : "+f"(c[0]), "+f"(c[1]), "+f"(c[2]), "+f"(c[3])
        : "r"(a[0]), "r"(a[1]), "r"(a[2]), "r"(a[3]), "r"(b[0]), "r"(b[1]));
}
__device__ __forceinline__ void cp_async16(unsigned dst, const void* src) {
    asm volatile("cp.async.cg.shared.global [%0], [%1], 16;"
                 :: "r"(dst), "l"(src) : "memory");
}
__device__ __forceinline__ void cp_commit() {
    asm volatile("cp.async.commit_group;" ::: "memory");
}
template<int N> __device__ __forceinline__ void cp_wait() {
    asm volatile("cp.async.wait_group %0;" :: "n"(N) : "memory");
}

union F2U { float2 f; unsigned long long u; };
__device__ __forceinline__ float2 ffma2(float2 a, float2 b, float2 c) {
    F2U A, Bv, C, D;
    A.f = a; Bv.f = b; C.f = c;
    asm("fma.rn.f32x2 %0, %1, %2, %3;"
        : "=l"(D.u) : "l"(A.u), "l"(Bv.u), "l"(C.u));
    return D.f;
}
__device__ __forceinline__ float2 dup2(float a) { return make_float2(a, a); }

// pack two fp32 into f16x2 (plain round)
__device__ __forceinline__ unsigned round2(float x, float y) {
    __half2 h2 = __halves2half2(__float2half_rn(x), __float2half_rn(y));
    return *reinterpret_cast<unsigned*>(&h2);
}
// pack 8 fp32 -> uint4 fp16
__device__ __forceinline__ uint4 round8(const float4& a, const float4& b) {
    uint4 o;
    o.x = round2(a.x, a.y);
    o.y = round2(a.z, a.w);
    o.z = round2(b.x, b.y);
    o.w = round2(b.z, b.w);
    return o;
}

// ============================================================================
// Prep: W transpose + fp16 round only (v1 copy folded into qkv epilogue).
// ============================================================================
__global__ void prep_kernel(const float* __restrict__ Wk,
                            const float* __restrict__ Wq,
                            const float* __restrict__ Wv)
{
    int ng = blockIdx.x;
    int m  = ng >> 6;
    int n  = ng & 63;
    const float* __restrict__ W = (m == 0) ? Wk : (m == 1) ? Wq : Wv;
    for (int k = threadIdx.x; k < C_; k += blockDim.x) {
        g_Wt_h[(size_t)ng * C_ + k] = __float2half_rn(W[(size_t)k * H_ + n]);
    }
}

// ============================================================================
// QKV GEMM on mma.sync fp16, 1-pass: D = fp16(x) . fp16(W), fp32 acc.
// Per CTA: 128 rows x 64 cols, K=768 in 12 stages of BK=64.
// A (x) via register prefetch + convert; B (W) via cp.async (already fp16).
// V epilogue also writes the v1 passthrough output (it reads v1 anyway).
// 2 CTAs/SM (NOT 3 — reg cap 84 causes pipelined-loop spills; R9 regression).
// ============================================================================
#define QK_STAGES 12
#define SA(b) ((b)*24576)
#define SB(b) ((b)*24576 + 16384)
#define QM_SMEM 49152

__global__ __launch_bounds__(256, 2)
void qkv_mma_kernel(const float* __restrict__ x, const float* __restrict__ v1,
                    const float* __restrict__ lamb_p,
                    float* __restrict__ v1dst)
{
    extern __shared__ char smem[];
    const unsigned sb = smem_u32(smem);
    const int tid  = threadIdx.x;
    const int warp = tid >> 5;
    const int lane = tid & 31;
    const int wm   = warp & 3;
    const int wn   = warp >> 2;
    const int mat  = blockIdx.x;       // 0:K 1:Q 2:V
    const int row0 = blockIdx.y * 128;

    float4 pa[4][2];
    const int arow = tid >> 3;
    const int ac8  = tid & 7;
    const unsigned bsw = ((ac8 * 16) ^ ((arow & 7) << 4));

    auto issue_b = [&](int k0, int buf) {
        #pragma unroll
        for (int it = 0; it < 2; it++) {
            int row = arow + it * 32;      // 0..63
            const void* src = &g_Wt_h[(size_t)(mat * 64 + row) * C_ + k0 + ac8 * 8];
            cp_async16(sb + SB(buf) + row * 128 + bsw, src);
        }
        cp_commit();
    };
    auto load_a = [&](int k0) {
        #pragma unroll
        for (int it = 0; it < 4; it++) {
            int row = arow + it * 32;
            const float* p = &x[(size_t)(row0 + row) * C_ + k0 + ac8 * 8];
            pa[it][0] = *reinterpret_cast<const float4*>(p);
            pa[it][1] = *reinterpret_cast<const float4*>(p + 4);
        }
    };
    auto store_a = [&](int buf) {
        #pragma unroll
        for (int it = 0; it < 4; it++) {
            int row = arow + it * 32;
            unsigned boff = row * 128 + ((ac8 * 16) ^ ((row & 7) << 4));
            *reinterpret_cast<uint4*>(smem + SA(buf) + boff) =
                round8(pa[it][0], pa[it][1]);
        }
    };

    const int r   = lane & 7;
    const int sel = lane >> 3;
    const unsigned rx = r << 4;
    unsigned rowA[2], kselA = (sel >> 1) * 16;
    #pragma unroll
    for (int mt = 0; mt < 2; mt++)
        rowA[mt] = (wm * 32 + mt * 16 + r + (sel & 1) * 8) * 128;
    unsigned rowB[2], kselB = (sel & 1) * 16;
    #pragma unroll
    for (int pt = 0; pt < 2; pt++)
        rowB[pt] = (wn * 32 + pt * 16 + r + ((sel & 2) ? 8 : 0)) * 128;

    float acc[2][4][4];
    #pragma unroll
    for (int mt = 0; mt < 2; mt++)
        #pragma unroll
        for (int nt = 0; nt < 4; nt++)
            #pragma unroll
            for (int e = 0; e < 4; e++) acc[mt][nt][e] = 0.0f;

    issue_b(0, 0);
    load_a(0);
    store_a(0);
    cp_wait<0>();
    __syncthreads();

    for (int t = 0; t < QK_STAGES; t++) {
        const int cur = t & 1;
        if (t + 1 < QK_STAGES) {
            issue_b((t + 1) * 64, (t + 1) & 1);
            load_a((t + 1) * 64);
        }

        const unsigned sa = sb + SA(cur);
        const unsigned sbh = sb + SB(cur);

        #pragma unroll
        for (int ks = 0; ks < 4; ks++) {
            const unsigned kb = ks * 32;
            unsigned aH[2][4], bH[2][4];
            #pragma unroll
            for (int mt = 0; mt < 2; mt++) {
                unsigned off = ((kb + kselA) ^ rx);
                ldsm4(aH[mt], sa + rowA[mt] + off);
            }
            #pragma unroll
            for (int pt = 0; pt < 2; pt++) {
                unsigned off = ((kb + kselB) ^ rx);
                ldsm4(bH[pt], sbh + rowB[pt] + off);
            }
            #pragma unroll
            for (int mt = 0; mt < 2; mt++)
                #pragma unroll
                for (int nt = 0; nt < 4; nt++)
                    mma_f16(acc[mt][nt], aH[mt], &bH[nt >> 1][(nt & 1) * 2]);
        }
        __syncthreads();
        if (t + 1 < QK_STAGES) {
            store_a((t + 1) & 1);
            cp_wait<0>();
            __syncthreads();
        }
    }

    // ---- epilogue ----
    const float lam = *lamb_p;
    const int qr = lane >> 2;
    const int qc = (lane & 3) * 2;
    #pragma unroll
    for (int mt = 0; mt < 2; mt++)
        #pragma unroll
        for (int nt = 0; nt < 4; nt++)
            #pragma unroll
            for (int half = 0; half < 2; half++) {
                int row = row0 + wm * 32 + mt * 16 + qr + half * 8;
                int col = wn * 32 + nt * 8 + qc;
                float vx = acc[mt][nt][half * 2];
                float vy = acc[mt][nt][half * 2 + 1];
                size_t off = (size_t)row * H_ + col;
                if (mat == 0) {
                    *reinterpret_cast<unsigned*>(&g_Kh[off]) = round2(vx, vy);
                } else if (mat == 1) {
                    *reinterpret_cast<unsigned*>(&g_Qh[off]) = round2(vx, vy);
                } else {
                    float2 vv = *reinterpret_cast<const float2*>(&v1[off]);
                    if (v1dst != nullptr)
                        *reinterpret_cast<float2*>(&v1dst[off]) = vv;  // passthrough
                    vx = (1.0f - lam) * vx + lam * vv.x;
                    vy = (1.0f - lam) * vy + lam * vv.y;
                    *reinterpret_cast<unsigned*>(&g_Vh[off]) = round2(vx, vy);
                }
            }
}

// ============================================================================
// Tensor-core flash attention (fp16 1-pass S, 1-pass PV), PAIRED q-tiles:
// CTA (b, p) processes qt = 15-p then qt = p -> exactly 34 k-blocks each,
// 128 CTAs = one balanced wave on 148 SMs.
// ============================================================================
#define AT_QO   34816
#define AT_KV(b) (AT_QO + (b)*16384)
#define AT_SMEM (AT_QO + 2*16384)
#define OTS 132

__global__ __launch_bounds__(256, 1)
void attn_tc_kernel(const float* __restrict__ Wproj,
                    const float* __restrict__ bproj,
                    float* __restrict__ out)
{
    extern __shared__ char smem[];
    const unsigned sb = smem_u32(smem);
    const int bid  = blockIdx.x;          // 0..127
    const int b    = bid & 15;
    const int p    = bid >> 4;             // 0..7
    const int tid  = threadIdx.x;
    const int warp = tid >> 5;
    const int lane = tid & 31;
    const int r    = lane & 7;
    const int sel  = lane >> 3;
    const unsigned rx = r << 4;
    const int rowbase = b * T_;
    const size_t baseo = (size_t)b * T_ * H_;
    const int tx = tid & 15;
    const int ty = tid >> 4;

    auto issue_kv = [&](int kb, int buf) {
        const __half* srcs[2] = {g_Kh, g_Vh};
        const unsigned dbase = sb + AT_KV(buf);
        #pragma unroll
        for (int it = 0; it < 4; it++) {
            int idx = tid + it * 256;          // 0..1023
            int arr = idx >> 9;
            int row = (idx >> 3) & 63;
            int c   = idx & 7;
            const void* src = &srcs[arr][(size_t)(rowbase + kb * 64 + row) * H_ + c * 8];
            unsigned dst = dbase + arr * 8192 + row * 128 + ((c * 16) ^ ((row & 7) << 4));
            cp_async16(dst, src);
        }
        cp_commit();
    };

    #pragma unroll 1
    for (int tile = 0; tile < 2; tile++) {
        const int qt  = tile ? p : (15 - p);   // heavy tile first
        const int q0  = qt * 128;
        const int nkb = 2 * qt + 2;

        issue_kv(0, 0);

        // stage Q tile into smem
        #pragma unroll
        for (int it = 0; it < 4; it++) {
            int idx = tid + it * 256;          // 0..1023
            int row = (idx >> 3) & 127;
            int c   = idx & 7;
            uint4 v = *reinterpret_cast<const uint4*>(
                &g_Qh[(size_t)(rowbase + q0 + row) * H_ + c * 8]);
            *reinterpret_cast<uint4*>(
                smem + row * 128 + ((c * 16) ^ ((row & 7) << 4))) = v;
        }
        cp_wait<0>();
        __syncthreads();

        unsigned qh[4][4];
        {
            int rowA = warp * 16 + r + (sel & 1) * 8;
            unsigned rb = rowA * 128;
            #pragma unroll
            for (int ks = 0; ks < 4; ks++) {
                unsigned off = ((ks * 32 + (sel >> 1) * 16) ^ rx);
                ldsm4(qh[ks], sb + rb + off);
            }
        }

        float oacc[8][4];
        #pragma unroll
        for (int j = 0; j < 8; j++)
            #pragma unroll
            for (int e = 0; e < 4; e++) oacc[j][e] = 0.0f;
        float mi[2] = {-1e30f, -1e30f}, li[2] = {0.0f, 0.0f};

        for (int kb = 0; kb < nkb; kb++) {
            const unsigned kvb = sb + AT_KV(kb & 1);
            cp_wait<0>();
            __syncthreads();
            if (kb + 1 < nkb) issue_kv(kb + 1, (kb + 1) & 1);

            float sacc[8][4];
            #pragma unroll
            for (int j = 0; j < 8; j++)
                #pragma unroll
                for (int e = 0; e < 4; e++) sacc[j][e] = 0.0f;

            #pragma unroll
            for (int ks = 0; ks < 4; ks++) {
                unsigned kh[4][4];
                const int rk = r + ((sel & 2) ? 8 : 0);
                const unsigned koff = ((ks * 32 + (sel & 1) * 16) ^ rx);
                #pragma unroll
                for (int u = 0; u < 4; u++) {
                    unsigned rb = (u * 16 + rk) * 128;
                    ldsm4(kh[u], kvb + rb + koff);
                }
                #pragma unroll
                for (int u = 0; u < 4; u++)
                    #pragma unroll
                    for (int nn = 0; nn < 2; nn++)
                        mma_f16(sacc[u * 2 + nn], qh[ks], &kh[u][nn * 2]);
            }

            const float scale = 0.125f;
            if (kb * 64 + 63 > q0 + warp * 16) {
                #pragma unroll
                for (int j = 0; j < 8; j++)
                    #pragma unroll
                    for (int e = 0; e < 4; e++) {
                        int key  = kb * 64 + j * 8 + (lane & 3) * 2 + (e & 1);
                        int qrow = q0 + warp * 16 + (lane >> 2) + (e >> 1) * 8;
                        float v = sacc[j][e] * scale;
                        sacc[j][e] = (key <= qrow) ? v : -1e30f;
                    }
            } else {
                #pragma unroll
                for (int j = 0; j < 8; j++)
                    #pragma unroll
                    for (int e = 0; e < 4; e++) sacc[j][e] *= scale;
            }

            #pragma unroll
            for (int h = 0; h < 2; h++) {
                float mx = -1e30f;
                #pragma unroll
                for (int j = 0; j < 8; j++)
                    mx = fmaxf(mx, fmaxf(sacc[j][h*2], sacc[j][h*2+1]));
                mx = fmaxf(mx, __shfl_xor_sync(0xffffffffu, mx, 1));
                mx = fmaxf(mx, __shfl_xor_sync(0xffffffffu, mx, 2));
                float mnew = fmaxf(mi[h], mx);
                float corr = __expf(mi[h] - mnew);
                mi[h] = mnew;
                float rs = 0.0f;
                #pragma unroll
                for (int j = 0; j < 8; j++) {
                    float p0 = __expf(sacc[j][h*2]   - mnew);
                    float p1 = __expf(sacc[j][h*2+1] - mnew);
                    sacc[j][h*2] = p0; sacc[j][h*2+1] = p1;
                    rs += p0 + p1;
                }
                rs += __shfl_xor_sync(0xffffffffu, rs, 1);
                rs += __shfl_xor_sync(0xffffffffu, rs, 2);
                li[h] = li[h] * corr + rs;
                #pragma unroll
                for (int j = 0; j < 8; j++) {
                    oacc[j][h*2]   *= corr;
                    oacc[j][h*2+1] *= corr;
                }
            }

            unsigned pfh[4][4];
            #pragma unroll
            for (int kt = 0; kt < 4; kt++) {
                pfh[kt][0] = round2(sacc[2*kt][0],   sacc[2*kt][1]);
                pfh[kt][1] = round2(sacc[2*kt][2],   sacc[2*kt][3]);
                pfh[kt][2] = round2(sacc[2*kt+1][0], sacc[2*kt+1][1]);
                pfh[kt][3] = round2(sacc[2*kt+1][2], sacc[2*kt+1][3]);
            }

            #pragma unroll
            for (int kt = 0; kt < 4; kt++) {
                unsigned vh[4][4];
                const unsigned rb = (kt * 16 + (sel & 1) * 8 + r) * 128;
                #pragma unroll
                for (int u = 0; u < 4; u++) {
                    unsigned off = (((2 * u + (sel >> 1)) * 16) ^ rx);
                    ldsm4_t(vh[u], kvb + 8192 + rb + off);
                }
                #pragma unroll
                for (int u = 0; u < 4; u++)
                    #pragma unroll
                    for (int nn = 0; nn < 2; nn++)
                        mma_f16(oacc[u * 2 + nn], pfh[kt], &vh[u][nn * 2]);
            }
        }

        // ---- epilogue: normalize, stage O^T (reuse Q smem), fused Wproj ----
        __syncthreads();
        float* Ot = reinterpret_cast<float*>(smem);
        {
            float inv0 = 1.0f / li[0], inv1 = 1.0f / li[1];
            #pragma unroll
            for (int j = 0; j < 8; j++)
                #pragma unroll
                for (int e = 0; e < 4; e++) {
                    int qrel = warp * 16 + (lane >> 2) + (e >> 1) * 8;
                    int d    = j * 8 + (lane & 3) * 2 + (e & 1);
                    Ot[d * OTS + qrel] = oacc[j][e] * ((e >> 1) ? inv1 : inv0);
                }
        }
        __syncthreads();

        float2 r2[8][2];
        #pragma unroll
        for (int i = 0; i < 8; i++) {
            r2[i][0] = make_float2(0.f, 0.f);
            r2[i][1] = make_float2(0.f, 0.f);
        }
        #pragma unroll 4
        for (int d = 0; d < 64; d++) {
            float4 a0 = *reinterpret_cast<const float4*>(&Ot[d * OTS + ty * 8]);
            float4 a1 = *reinterpret_cast<const float4*>(&Ot[d * OTS + ty * 8 + 4]);
            float4 w  = *reinterpret_cast<const float4*>(&Wproj[d * 64 + tx * 4]);
            float2 w01 = make_float2(w.x, w.y);
            float2 w23 = make_float2(w.z, w.w);
            float a[8] = {a0.x, a0.y, a0.z, a0.w, a1.x, a1.y, a1.z, a1.w};
            #pragma unroll
            for (int i = 0; i < 8; i++) {
                float2 ad = dup2(a[i]);
                r2[i][0] = ffma2(ad, w01, r2[i][0]);
                r2[i][1] = ffma2(ad, w23, r2[i][1]);
            }
        }
        float4 bb = *reinterpret_cast<const float4*>(&bproj[tx * 4]);
        #pragma unroll
        for (int i = 0; i < 8; i++) {
            float4 ov = make_float4(r2[i][0].x + bb.x, r2[i][0].y + bb.y,
                                    r2[i][1].x + bb.z, r2[i][1].y + bb.w);
            *reinterpret_cast<float4*>(
                &out[baseo + (size_t)(q0 + ty * 8 + i) * H_ + tx * 4]) = ov;
        }
        __syncthreads();   // Ot reads done before next tile re-stages Q
    }
}

extern "C" void kernel_launch(void* const* d_in, const int* in_sizes, int n_in,
                              void* d_out, int out_size)
{
    const float* x     = (const float*)d_in[0];
    const float* v1    = (const float*)d_in[1];
    const float* Wk    = (const float*)d_in[2];
    const float* Wq    = (const float*)d_in[3];
    const float* Wv    = (const float*)d_in[4];
    const float* Wproj = (const float*)d_in[5];
    const float* bproj = (const float*)d_in[6];
    const float* lamb  = (const float*)d_in[7];
    float* out = (float*)d_out;

    cudaFuncSetAttribute(qkv_mma_kernel,
                         cudaFuncAttributeMaxDynamicSharedMemorySize, QM_SMEM);
    cudaFuncSetAttribute(attn_tc_kernel,
                         cudaFuncAttributeMaxDynamicSharedMemorySize, AT_SMEM);

    float* v1dst = (out_size >= 2 * BT_ * H_) ? (out + (size_t)BT_ * H_) : nullptr;
    prep_kernel<<<192, 256>>>(Wk, Wq, Wv);
    qkv_mma_kernel<<<dim3(3, BT_ / 128), 256, QM_SMEM>>>(x, v1, lamb, v1dst);
    attn_tc_kernel<<<16 * 8, 256, AT_SMEM>>>(Wproj, bproj, out);
}

// round 12
// speedup vs baseline: 1.0895x; 1.0895x over previous
#include <cuda_runtime.h>
#include <cuda_fp16.h>
#include <math.h>

#define B_  16
#define T_  2048
#define C_  768
#define H_  64
#define BT_ (B_*T_)

// Scratch (allocation-free rule: device globals) — all fp16-rounded
__device__ __half g_Qh[BT_*H_];
__device__ __half g_Kh[BT_*H_];
__device__ __half g_Vh[BT_*H_];
// W transposed, fp16-rounded: rows ng = m*64+n (m: 0=K,1=Q,2=V), cols k
__device__ __half g_Wt_h[192*768];

// ---------------------------------------------------------------------------
// helpers
// ---------------------------------------------------------------------------
__device__ __forceinline__ unsigned smem_u32(const void* p) {
    unsigned a;
    asm("{ .reg .u64 t; cvta.to.shared.u64 t, %1; cvt.u32.u64 %0, t; }"
        : "=r"(a) : "l"(p));
    return a;
}
__device__ __forceinline__ void ldsm4(unsigned* r, unsigned addr) {
    asm volatile("ldmatrix.sync.aligned.m8n8.x4.shared.b16 {%0,%1,%2,%3}, [%4];"
                 : "=r"(r[0]), "=r"(r[1]), "=r"(r[2]), "=r"(r[3]) : "r"(addr));
}
__device__ __forceinline__ void ldsm4_t(unsigned* r, unsigned addr) {
    asm volatile("ldmatrix.sync.aligned.m8n8.x4.trans.shared.b16 {%0,%1,%2,%3}, [%4];"
                 : "=r"(r[0]), "=r"(r[1]), "=r"(r[2]), "=r"(r[3]) : "r"(addr));
}
__device__ __forceinline__ void mma_f16(float* c, const unsigned* a, const unsigned* b) {
    asm volatile(
        "mma.sync.aligned.m16n8k16.row.col.f32.f16.f16.f32 "
        "{%0,%1,%2,%3}, {%4,%5,%6,%7}, {%8,%9}, {%0,%1,%2,%3};"
        : "+f"(c[0]), "+f"(c[1]), "+f"(c[2]), "+f"(c[3])
        : "r"(a[0]), "r"(a[1]), "r"(a[2]), "r"(a[3]), "r"(b[0]), "r"(b[1]));
}
__device__ __forceinline__ void cp_async16(unsigned dst, const void* src) {
    asm volatile("cp.async.cg.shared.global [%0], [%1], 16;"
                 :: "r"(dst), "l"(src) : "memory");
}
__device__ __forceinline__ void cp_commit() {
    asm volatile("cp.async.commit_group;" ::: "memory");
}
template<int N> __device__ __forceinline__ void cp_wait() {
    asm volatile("cp.async.wait_group %0;" :: "n"(N) : "memory");
}
// packed fp16x2 exp2
__device__ __forceinline__ unsigned h2exp2(unsigned d) {
    unsigned r;
    asm("ex2.approx.f16x2 %0, %1;" : "=r"(r) : "r"(d));
    return r;
}

union F2U { float2 f; unsigned long long u; };
__device__ __forceinline__ float2 ffma2(float2 a, float2 b, float2 c) {
    F2U A, Bv, C, D;
    A.f = a; Bv.f = b; C.f = c;
    asm("fma.rn.f32x2 %0, %1, %2, %3;"
        : "=l"(D.u) : "l"(A.u), "l"(Bv.u), "l"(C.u));
    return D.f;
}
__device__ __forceinline__ float2 dup2(float a) { return make_float2(a, a); }

// pack two fp32 into f16x2 (plain round)
__device__ __forceinline__ unsigned round2(float x, float y) {
    __half2 h2 = __halves2half2(__float2half_rn(x), __float2half_rn(y));
    return *reinterpret_cast<unsigned*>(&h2);
}
// pack 8 fp32 -> uint4 fp16
__device__ __forceinline__ uint4 round8(const float4& a, const float4& b) {
    uint4 o;
    o.x = round2(a.x, a.y);
    o.y = round2(a.z, a.w);
    o.z = round2(b.x, b.y);
    o.w = round2(b.z, b.w);
    return o;
}

// ============================================================================
// Prep: W transpose + fp16 round only (v1 copy folded into qkv epilogue).
// ============================================================================
__global__ void prep_kernel(const float* __restrict__ Wk,
                            const float* __restrict__ Wq,
                            const float* __restrict__ Wv)
{
    int ng = blockIdx.x;
    int m  = ng >> 6;
    int n  = ng & 63;
    const float* __restrict__ W = (m == 0) ? Wk : (m == 1) ? Wq : Wv;
    for (int k = threadIdx.x; k < C_; k += blockDim.x) {
        g_Wt_h[(size_t)ng * C_ + k] = __float2half_rn(W[(size_t)k * H_ + n]);
    }
}

// ============================================================================
// QKV GEMM on mma.sync fp16, 1-pass: D = fp16(x) . fp16(W), fp32 acc.
// (unchanged from R10/R11; V epilogue writes v1 passthrough)
// ============================================================================
#define QK_STAGES 12
#define SA(b) ((b)*24576)
#define SB(b) ((b)*24576 + 16384)
#define QM_SMEM 49152

__global__ __launch_bounds__(256, 2)
void qkv_mma_kernel(const float* __restrict__ x, const float* __restrict__ v1,
                    const float* __restrict__ lamb_p,
                    float* __restrict__ v1dst)
{
    extern __shared__ char smem[];
    const unsigned sb = smem_u32(smem);
    const int tid  = threadIdx.x;
    const int warp = tid >> 5;
    const int lane = tid & 31;
    const int wm   = warp & 3;
    const int wn   = warp >> 2;
    const int mat  = blockIdx.x;       // 0:K 1:Q 2:V
    const int row0 = blockIdx.y * 128;

    float4 pa[4][2];
    const int arow = tid >> 3;
    const int ac8  = tid & 7;
    const unsigned bsw = ((ac8 * 16) ^ ((arow & 7) << 4));

    auto issue_b = [&](int k0, int buf) {
        #pragma unroll
        for (int it = 0; it < 2; it++) {
            int row = arow + it * 32;      // 0..63
            const void* src = &g_Wt_h[(size_t)(mat * 64 + row) * C_ + k0 + ac8 * 8];
            cp_async16(sb + SB(buf) + row * 128 + bsw, src);
        }
        cp_commit();
    };
    auto load_a = [&](int k0) {
        #pragma unroll
        for (int it = 0; it < 4; it++) {
            int row = arow + it * 32;
            const float* p = &x[(size_t)(row0 + row) * C_ + k0 + ac8 * 8];
            pa[it][0] = *reinterpret_cast<const float4*>(p);
            pa[it][1] = *reinterpret_cast<const float4*>(p + 4);
        }
    };
    auto store_a = [&](int buf) {
        #pragma unroll
        for (int it = 0; it < 4; it++) {
            int row = arow + it * 32;
            unsigned boff = row * 128 + ((ac8 * 16) ^ ((row & 7) << 4));
            *reinterpret_cast<uint4*>(smem + SA(buf) + boff) =
                round8(pa[it][0], pa[it][1]);
        }
    };

    const int r   = lane & 7;
    const int sel = lane >> 3;
    const unsigned rx = r << 4;
    unsigned rowA[2], kselA = (sel >> 1) * 16;
    #pragma unroll
    for (int mt = 0; mt < 2; mt++)
        rowA[mt] = (wm * 32 + mt * 16 + r + (sel & 1) * 8) * 128;
    unsigned rowB[2], kselB = (sel & 1) * 16;
    #pragma unroll
    for (int pt = 0; pt < 2; pt++)
        rowB[pt] = (wn * 32 + pt * 16 + r + ((sel & 2) ? 8 : 0)) * 128;

    float acc[2][4][4];
    #pragma unroll
    for (int mt = 0; mt < 2; mt++)
        #pragma unroll
        for (int nt = 0; nt < 4; nt++)
            #pragma unroll
            for (int e = 0; e < 4; e++) acc[mt][nt][e] = 0.0f;

    issue_b(0, 0);
    load_a(0);
    store_a(0);
    cp_wait<0>();
    __syncthreads();

    for (int t = 0; t < QK_STAGES; t++) {
        const int cur = t & 1;
        if (t + 1 < QK_STAGES) {
            issue_b((t + 1) * 64, (t + 1) & 1);
            load_a((t + 1) * 64);
        }

        const unsigned sa = sb + SA(cur);
        const unsigned sbh = sb + SB(cur);

        #pragma unroll
        for (int ks = 0; ks < 4; ks++) {
            const unsigned kb = ks * 32;
            unsigned aH[2][4], bH[2][4];
            #pragma unroll
            for (int mt = 0; mt < 2; mt++) {
                unsigned off = ((kb + kselA) ^ rx);
                ldsm4(aH[mt], sa + rowA[mt] + off);
            }
            #pragma unroll
            for (int pt = 0; pt < 2; pt++) {
                unsigned off = ((kb + kselB) ^ rx);
                ldsm4(bH[pt], sbh + rowB[pt] + off);
            }
            #pragma unroll
            for (int mt = 0; mt < 2; mt++)
                #pragma unroll
                for (int nt = 0; nt < 4; nt++)
                    mma_f16(acc[mt][nt], aH[mt], &bH[nt >> 1][(nt & 1) * 2]);
        }
        __syncthreads();
        if (t + 1 < QK_STAGES) {
            store_a((t + 1) & 1);
            cp_wait<0>();
            __syncthreads();
        }
    }

    // ---- epilogue ----
    const float lam = *lamb_p;
    const int qr = lane >> 2;
    const int qc = (lane & 3) * 2;
    #pragma unroll
    for (int mt = 0; mt < 2; mt++)
        #pragma unroll
        for (int nt = 0; nt < 4; nt++)
            #pragma unroll
            for (int half = 0; half < 2; half++) {
                int row = row0 + wm * 32 + mt * 16 + qr + half * 8;
                int col = wn * 32 + nt * 8 + qc;
                float vx = acc[mt][nt][half * 2];
                float vy = acc[mt][nt][half * 2 + 1];
                size_t off = (size_t)row * H_ + col;
                if (mat == 0) {
                    *reinterpret_cast<unsigned*>(&g_Kh[off]) = round2(vx, vy);
                } else if (mat == 1) {
                    *reinterpret_cast<unsigned*>(&g_Qh[off]) = round2(vx, vy);
                } else {
                    float2 vv = *reinterpret_cast<const float2*>(&v1[off]);
                    if (v1dst != nullptr)
                        *reinterpret_cast<float2*>(&v1dst[off]) = vv;  // passthrough
                    vx = (1.0f - lam) * vx + lam * vv.x;
                    vy = (1.0f - lam) * vy + lam * vv.y;
                    *reinterpret_cast<unsigned*>(&g_Vh[off]) = round2(vx, vy);
                }
            }
}

// ============================================================================
// Tensor-core flash attention (fp16 1-pass S, 1-pass PV).
// Grid = 256 CTAs, heavy-first (R10 schedule — R11 pairing regressed).
// Softmax: base-2 fp16x2 ex2.approx; row-sums via ones-column MMA (li in
// the PV accumulator, corr-rescaled alongside oacc).
// ============================================================================
#define AT_QO   34816
#define AT_KV(b) (AT_QO + (b)*16384)
#define AT_SMEM (AT_QO + 2*16384)
#define OTS 132

__global__ __launch_bounds__(256, 1)
void attn_tc_kernel(const float* __restrict__ Wproj,
                    const float* __restrict__ bproj,
                    float* __restrict__ out)
{
    extern __shared__ char smem[];
    const unsigned sb = smem_u32(smem);
    const int bid  = blockIdx.x;
    const int b    = bid & 15;
    const int qt   = 15 - (bid >> 4);        // heavy tiles first
    const int tid  = threadIdx.x;
    const int warp = tid >> 5;
    const int lane = tid & 31;
    const int r    = lane & 7;
    const int sel  = lane >> 3;
    const unsigned rx = r << 4;
    const int q0   = qt * 128;
    const int rowbase = b * T_;
    const int nkb  = 2 * qt + 2;

    // ones-column B fragment (n=0 col of an n8 tile): lanes 0..3 hold (1,1)
    unsigned b_ones[2];
    b_ones[0] = b_ones[1] = ((lane >> 2) == 0) ? 0x3C003C00u : 0u;

    auto issue_kv = [&](int kb, int buf) {
        const __half* srcs[2] = {g_Kh, g_Vh};
        const unsigned dbase = sb + AT_KV(buf);
        #pragma unroll
        for (int it = 0; it < 4; it++) {
            int idx = tid + it * 256;          // 0..1023
            int arr = idx >> 9;
            int row = (idx >> 3) & 63;
            int c   = idx & 7;
            const void* src = &srcs[arr][(size_t)(rowbase + kb * 64 + row) * H_ + c * 8];
            unsigned dst = dbase + arr * 8192 + row * 128 + ((c * 16) ^ ((row & 7) << 4));
            cp_async16(dst, src);
        }
        cp_commit();
    };

    issue_kv(0, 0);

    #pragma unroll
    for (int it = 0; it < 4; it++) {
        int idx = tid + it * 256;              // 0..1023
        int row = (idx >> 3) & 127;
        int c   = idx & 7;
        uint4 v = *reinterpret_cast<const uint4*>(
            &g_Qh[(size_t)(rowbase + q0 + row) * H_ + c * 8]);
        *reinterpret_cast<uint4*>(
            smem + row * 128 + ((c * 16) ^ ((row & 7) << 4))) = v;
    }
    cp_wait<0>();
    __syncthreads();

    unsigned qh[4][4];
    {
        int rowA = warp * 16 + r + (sel & 1) * 8;
        unsigned rb = rowA * 128;
        #pragma unroll
        for (int ks = 0; ks < 4; ks++) {
            unsigned off = ((ks * 32 + (sel >> 1) * 16) ^ rx);
            ldsm4(qh[ks], sb + rb + off);
        }
    }

    float oacc[8][4];
    float lacc[4];
    #pragma unroll
    for (int j = 0; j < 8; j++)
        #pragma unroll
        for (int e = 0; e < 4; e++) oacc[j][e] = 0.0f;
    #pragma unroll
    for (int e = 0; e < 4; e++) lacc[e] = 0.0f;
    float mi[2] = {-1e30f, -1e30f};

    for (int kb = 0; kb < nkb; kb++) {
        const unsigned kvb = sb + AT_KV(kb & 1);
        cp_wait<0>();
        __syncthreads();
        if (kb + 1 < nkb) issue_kv(kb + 1, (kb + 1) & 1);

        float sacc[8][4];
        #pragma unroll
        for (int j = 0; j < 8; j++)
            #pragma unroll
            for (int e = 0; e < 4; e++) sacc[j][e] = 0.0f;

        #pragma unroll
        for (int ks = 0; ks < 4; ks++) {
            unsigned kh[4][4];
            const int rk = r + ((sel & 2) ? 8 : 0);
            const unsigned koff = ((ks * 32 + (sel & 1) * 16) ^ rx);
            #pragma unroll
            for (int u = 0; u < 4; u++) {
                unsigned rb = (u * 16 + rk) * 128;
                ldsm4(kh[u], kvb + rb + koff);
            }
            #pragma unroll
            for (int u = 0; u < 4; u++)
                #pragma unroll
                for (int nn = 0; nn < 2; nn++)
                    mma_f16(sacc[u * 2 + nn], qh[ks], &kh[u][nn * 2]);
        }

        // ---- scale (base-2 domain) + causal mask ----
        const float alpha = 0.18033688f;   // 0.125 * log2(e)
        if (kb * 64 + 63 > q0 + warp * 16) {
            #pragma unroll
            for (int j = 0; j < 8; j++)
                #pragma unroll
                for (int e = 0; e < 4; e++) {
                    int key  = kb * 64 + j * 8 + (lane & 3) * 2 + (e & 1);
                    int qrow = q0 + warp * 16 + (lane >> 2) + (e >> 1) * 8;
                    float v = sacc[j][e] * alpha;
                    sacc[j][e] = (key <= qrow) ? v : -1e30f;
                }
        } else {
            #pragma unroll
            for (int j = 0; j < 8; j++)
                #pragma unroll
                for (int e = 0; e < 4; e++) sacc[j][e] *= alpha;
        }

        // ---- online softmax: max + fp16x2 ex2 (P fragments built directly) ----
        unsigned pfh[4][4];
        #pragma unroll
        for (int h = 0; h < 2; h++) {
            float mx = -1e30f;
            #pragma unroll
            for (int j = 0; j < 8; j++)
                mx = fmaxf(mx, fmaxf(sacc[j][h*2], sacc[j][h*2+1]));
            mx = fmaxf(mx, __shfl_xor_sync(0xffffffffu, mx, 1));
            mx = fmaxf(mx, __shfl_xor_sync(0xffffffffu, mx, 2));
            float mnew = fmaxf(mi[h], mx);
            float corr = exp2f(mi[h] - mnew);
            mi[h] = mnew;
            #pragma unroll
            for (int j = 0; j < 8; j++) {
                __half2 d2 = __floats2half2_rn(sacc[j][h*2]   - mnew,
                                               sacc[j][h*2+1] - mnew);
                pfh[j >> 1][(j & 1) * 2 + h] =
                    h2exp2(*reinterpret_cast<unsigned*>(&d2));
            }
            #pragma unroll
            for (int j = 0; j < 8; j++) {
                oacc[j][h*2]   *= corr;
                oacc[j][h*2+1] *= corr;
            }
            lacc[h*2]   *= corr;
            lacc[h*2+1] *= corr;
        }

        // ---- O += P V ; row-sum via ones-column MMA ----
        #pragma unroll
        for (int kt = 0; kt < 4; kt++) {
            unsigned vh[4][4];
            const unsigned rb = (kt * 16 + (sel & 1) * 8 + r) * 128;
            #pragma unroll
            for (int u = 0; u < 4; u++) {
                unsigned off = (((2 * u + (sel >> 1)) * 16) ^ rx);
                ldsm4_t(vh[u], kvb + 8192 + rb + off);
            }
            #pragma unroll
            for (int u = 0; u < 4; u++)
                #pragma unroll
                for (int nn = 0; nn < 2; nn++)
                    mma_f16(oacc[u * 2 + nn], pfh[kt], &vh[u][nn * 2]);
            mma_f16(lacc, pfh[kt], b_ones);
        }
    }

    // ---- epilogue: li from ones-column (quad-lane 0 holds col 0) ----
    __syncthreads();
    float li0 = __shfl_sync(0xffffffffu, lacc[0], lane & 28);
    float li1 = __shfl_sync(0xffffffffu, lacc[2], lane & 28);
    float* Ot = reinterpret_cast<float*>(smem);
    {
        float inv0 = 1.0f / li0, inv1 = 1.0f / li1;
        #pragma unroll
        for (int j = 0; j < 8; j++)
            #pragma unroll
            for (int e = 0; e < 4; e++) {
                int qrel = warp * 16 + (lane >> 2) + (e >> 1) * 8;
                int d    = j * 8 + (lane & 3) * 2 + (e & 1);
                Ot[d * OTS + qrel] = oacc[j][e] * ((e >> 1) ? inv1 : inv0);
            }
    }
    __syncthreads();

    const int tx = tid & 15;
    const int ty = tid >> 4;
    float2 r2[8][2];
    #pragma unroll
    for (int i = 0; i < 8; i++) {
        r2[i][0] = make_float2(0.f, 0.f);
        r2[i][1] = make_float2(0.f, 0.f);
    }
    #pragma unroll 4
    for (int d = 0; d < 64; d++) {
        float4 a0 = *reinterpret_cast<const float4*>(&Ot[d * OTS + ty * 8]);
        float4 a1 = *reinterpret_cast<const float4*>(&Ot[d * OTS + ty * 8 + 4]);
        float4 w  = *reinterpret_cast<const float4*>(&Wproj[d * 64 + tx * 4]);
        float2 w01 = make_float2(w.x, w.y);
        float2 w23 = make_float2(w.z, w.w);
        float a[8] = {a0.x, a0.y, a0.z, a0.w, a1.x, a1.y, a1.z, a1.w};
        #pragma unroll
        for (int i = 0; i < 8; i++) {
            float2 ad = dup2(a[i]);
            r2[i][0] = ffma2(ad, w01, r2[i][0]);
            r2[i][1] = ffma2(ad, w23, r2[i][1]);
        }
    }
    float4 bb = *reinterpret_cast<const float4*>(&bproj[tx * 4]);
    const size_t baseo = (size_t)b * T_ * H_;
    #pragma unroll
    for (int i = 0; i < 8; i++) {
        float4 ov = make_float4(r2[i][0].x + bb.x, r2[i][0].y + bb.y,
                                r2[i][1].x + bb.z, r2[i][1].y + bb.w);
        *reinterpret_cast<float4*>(
            &out[baseo + (size_t)(q0 + ty * 8 + i) * H_ + tx * 4]) = ov;
    }
}

extern "C" void kernel_launch(void* const* d_in, const int* in_sizes, int n_in,
                              void* d_out, int out_size)
{
    const float* x     = (const float*)d_in[0];
    const float* v1    = (const float*)d_in[1];
    const float* Wk    = (const float*)d_in[2];
    const float* Wq    = (const float*)d_in[3];
    const float* Wv    = (const float*)d_in[4];
    const float* Wproj = (const float*)d_in[5];
    const float* bproj = (const float*)d_in[6];
    const float* lamb  = (const float*)d_in[7];
    float* out = (float*)d_out;

    cudaFuncSetAttribute(qkv_mma_kernel,
                         cudaFuncAttributeMaxDynamicSharedMemorySize, QM_SMEM);
    cudaFuncSetAttribute(attn_tc_kernel,
                         cudaFuncAttributeMaxDynamicSharedMemorySize, AT_SMEM);

    float* v1dst = (out_size >= 2 * BT_ * H_) ? (out + (size_t)BT_ * H_) : nullptr;
    prep_kernel<<<192, 256>>>(Wk, Wq, Wv);
    qkv_mma_kernel<<<dim3(3, BT_ / 128), 256, QM_SMEM>>>(x, v1, lamb, v1dst);
    attn_tc_kernel<<<16 * B_, 256, AT_SMEM>>>(Wproj, bproj, out);
}